// round 2
// baseline (speedup 1.0000x reference)
#include <cuda_runtime.h>
#include <math.h>

#define NLV 8
#define TSZ 1024
#define THREADS 256
#define CTAS 592

// shared: table 16384 | w1t 1024 | w2 1024 | r1t 1024 | r2 4096 | r3 64
#define SMEM_FLOATS (16384 + 1024 + 1024 + 1024 + 4096 + 64)
#define SMEM_BYTES (SMEM_FLOATS * 4)

__global__ __launch_bounds__(THREADS) void ngp_kernel(
    const float* __restrict__ x,
    const float* __restrict__ table,
    const float* __restrict__ w1,
    const float* __restrict__ w2,
    const float* __restrict__ r1,
    const float* __restrict__ r2,
    const float* __restrict__ r3,
    float* __restrict__ out,
    int N, int4 ra, int4 rb)
{
    extern __shared__ float sm[];
    float* s_tab = sm;                 // 16384
    float* s_w1t = sm + 16384;         // 1024 (transposed: [j][k])
    float* s_w2  = s_w1t + 1024;       // 1024 ([j][k], row-major as given)
    float* s_r1t = s_w2 + 1024;        // 1024 (transposed)
    float* s_r2  = s_r1t + 1024;       // 4096
    float* s_r3  = s_r2 + 4096;        // 64

    const int tid = threadIdx.x;
    for (int i = tid; i < 16384; i += THREADS) s_tab[i] = table[i];
    for (int i = tid; i < 1024; i += THREADS) {
        int k = i & 15, j = i >> 4;
        s_w1t[i] = w1[k * 64 + j];
        s_r1t[i] = r1[k * 64 + j];
        s_w2[i]  = w2[i];
    }
    for (int i = tid; i < 4096; i += THREADS) s_r2[i] = r2[i];
    if (tid < 64) s_r3[tid] = r3[tid];
    __syncthreads();

    const int res[8] = {ra.x, ra.y, ra.z, ra.w, rb.x, rb.y, rb.z, rb.w};

    for (int i = blockIdx.x * THREADS + tid; i < N; i += CTAS * THREADS) {
        float x01 = x[3 * i + 0] + 0.5f;
        float y01 = x[3 * i + 1] + 0.5f;
        float z01 = x[3 * i + 2] + 0.5f;

        // ---------------- hash-grid encode -> hf[16] ----------------
        float hf[16];
        #pragma unroll
        for (int l = 0; l < NLV; l++) {
            float rf = (float)res[l];
            float fx = x01 * rf, fy = y01 * rf, fz = z01 * rf;
            float gx = floorf(fx), gy = floorf(fy), gz = floorf(fz);
            float wx = fx - gx, wy = fy - gy, wz = fz - gz;
            unsigned ix = (unsigned)(int)gx;
            unsigned iy = (unsigned)(int)gy;
            unsigned iz = (unsigned)(int)gz;
            unsigned hx0 = ix, hx1 = ix + 1u;
            unsigned hy0 = iy * 2654435761u, hy1 = hy0 + 2654435761u;
            unsigned hz0 = iz * 805459861u,  hz1 = hz0 + 805459861u;
            float wx0 = 1.f - wx, wy0 = 1.f - wy, wz0 = 1.f - wz;
            const float* tl = s_tab + l * (TSZ * 2);
            float f0 = 0.f, f1 = 0.f;
            #pragma unroll
            for (int c = 0; c < 8; c++) {
                unsigned h = ((c & 4) ? hx1 : hx0)
                           ^ ((c & 2) ? hy1 : hy0)
                           ^ ((c & 1) ? hz1 : hz0);
                unsigned idx = h & (TSZ - 1u);
                float wgt = ((c & 4) ? wx : wx0)
                          * ((c & 2) ? wy : wy0)
                          * ((c & 1) ? wz : wz0);
                float2 t = *(const float2*)(tl + idx * 2);
                f0 = fmaf(wgt, t.x, f0);
                f1 = fmaf(wgt, t.y, f1);
            }
            hf[l * 2]     = f0;
            hf[l * 2 + 1] = f1;
        }

        // ---------------- xyz MLP: 16 -> 64 (relu) -> 16 ----------------
        float h2[16];
        #pragma unroll
        for (int k = 0; k < 16; k++) h2[k] = 0.f;
        #pragma unroll 2
        for (int j = 0; j < 64; j++) {
            const float4* wv = (const float4*)(s_w1t + j * 16);
            float a0 = 0.f, a1 = 0.f, a2 = 0.f, a3 = 0.f;
            #pragma unroll
            for (int q = 0; q < 4; q++) {
                float4 v = wv[q];
                a0 = fmaf(hf[4 * q + 0], v.x, a0);
                a1 = fmaf(hf[4 * q + 1], v.y, a1);
                a2 = fmaf(hf[4 * q + 2], v.z, a2);
                a3 = fmaf(hf[4 * q + 3], v.w, a3);
            }
            float a = fmaxf((a0 + a1) + (a2 + a3), 0.f);
            const float4* uv = (const float4*)(s_w2 + j * 16);
            #pragma unroll
            for (int q = 0; q < 4; q++) {
                float4 u = uv[q];
                h2[4 * q + 0] = fmaf(a, u.x, h2[4 * q + 0]);
                h2[4 * q + 1] = fmaf(a, u.y, h2[4 * q + 1]);
                h2[4 * q + 2] = fmaf(a, u.z, h2[4 * q + 2]);
                h2[4 * q + 3] = fmaf(a, u.w, h2[4 * q + 3]);
            }
        }

        // ---------------- rgb: 16 -> 64 (relu) -> 64 (relu) -> 1 ----------------
        float g2[64];
        #pragma unroll
        for (int k = 0; k < 64; k++) g2[k] = 0.f;
        #pragma unroll 2
        for (int j = 0; j < 64; j++) {
            const float4* wv = (const float4*)(s_r1t + j * 16);
            float a0 = 0.f, a1 = 0.f, a2 = 0.f, a3 = 0.f;
            #pragma unroll
            for (int q = 0; q < 4; q++) {
                float4 v = wv[q];
                a0 = fmaf(h2[4 * q + 0], v.x, a0);
                a1 = fmaf(h2[4 * q + 1], v.y, a1);
                a2 = fmaf(h2[4 * q + 2], v.z, a2);
                a3 = fmaf(h2[4 * q + 3], v.w, a3);
            }
            float a = fmaxf((a0 + a1) + (a2 + a3), 0.f);
            const float4* rv = (const float4*)(s_r2 + j * 64);
            #pragma unroll
            for (int q = 0; q < 16; q++) {
                float4 u = rv[q];
                g2[4 * q + 0] = fmaf(a, u.x, g2[4 * q + 0]);
                g2[4 * q + 1] = fmaf(a, u.y, g2[4 * q + 1]);
                g2[4 * q + 2] = fmaf(a, u.z, g2[4 * q + 2]);
                g2[4 * q + 3] = fmaf(a, u.w, g2[4 * q + 3]);
            }
        }

        float z0 = 0.f, z1 = 0.f, z2 = 0.f, z3 = 0.f;
        const float4* r3v = (const float4*)s_r3;
        #pragma unroll
        for (int q = 0; q < 16; q++) {
            float4 u = r3v[q];
            z0 = fmaf(fmaxf(g2[4 * q + 0], 0.f), u.x, z0);
            z1 = fmaf(fmaxf(g2[4 * q + 1], 0.f), u.y, z1);
            z2 = fmaf(fmaxf(g2[4 * q + 2], 0.f), u.z, z2);
            z3 = fmaf(fmaxf(g2[4 * q + 3], 0.f), u.w, z3);
        }
        float z = (z0 + z1) + (z2 + z3);
        out[i] = 1.f / (1.f + expf(-z));
    }
}

extern "C" void kernel_launch(void* const* d_in, const int* in_sizes, int n_in,
                              void* d_out, int out_size) {
    const float* x     = (const float*)d_in[0];
    const float* table = (const float*)d_in[1];
    const float* w1    = (const float*)d_in[2];
    const float* w2    = (const float*)d_in[3];
    const float* r1    = (const float*)d_in[4];
    const float* r2    = (const float*)d_in[5];
    const float* r3    = (const float*)d_in[6];
    float* out = (float*)d_out;
    int N = in_sizes[0] / 3;

    // Replicate numpy's RES computation with the SAME libm the reference uses
    // on this host (RES[7] = floor(2*B^7) sits at 10 +/- 1e-14 — do not hardcode).
    double b = exp(log(5.0) / 7.0);   // np.exp(np.log(20*0.5/2)/(L-1))
    int rs[8];
    for (int l = 0; l < 8; l++) rs[l] = (int)floor(2.0 * pow(b, (double)l));
    int4 ra = make_int4(rs[0], rs[1], rs[2], rs[3]);
    int4 rb = make_int4(rs[4], rs[5], rs[6], rs[7]);

    cudaFuncSetAttribute(ngp_kernel, cudaFuncAttributeMaxDynamicSharedMemorySize, SMEM_BYTES);
    ngp_kernel<<<CTAS, THREADS, SMEM_BYTES>>>(x, table, w1, w2, r1, r2, r3,
                                              out, N, ra, rb);
}

// round 3
// speedup vs baseline: 5.8427x; 5.8427x over previous
#include <cuda_runtime.h>
#include <cuda_bf16.h>
#include <math.h>

#define THREADS 256
#define WARPS 8
#define CTAS 296

// dynamic smem byte offsets
#define OFF_TAB 0                       // 16384 f32           (65536 B)
#define OFF_W1T 65536                   // [n=64][k=16] bf16   ( 2048 B)
#define OFF_R1T (OFF_W1T + 2048)        // [n=64][k=16] bf16   ( 2048 B)
#define OFF_W2T (OFF_R1T + 2048)        // [n=16][k=72] bf16   ( 2304 B)
#define OFF_R2T (OFF_W2T + 2304)        // [n=64][k=72] bf16   ( 9216 B)
#define OFF_R3T (OFF_R2T + 9216)        // [n= 8][k=72] bf16   ( 1152 B)
#define OFF_STG (OFF_R3T + 1152)        // per warp: 8 kpairs * 36 words (1152 B)
#define SMEM_BYTES (OFF_STG + WARPS * 1152)   // 91520 B

__device__ __forceinline__ unsigned pack_bf16(float lo, float hi) {
    unsigned d;
    asm("cvt.rn.bf16x2.f32 %0, %1, %2;" : "=r"(d) : "f"(hi), "f"(lo));
    return d;
}

__device__ __forceinline__ void mma_bf16(float* c, const unsigned* a,
                                         unsigned b0, unsigned b1) {
    asm volatile(
        "mma.sync.aligned.m16n8k16.row.col.f32.bf16.bf16.f32 "
        "{%0,%1,%2,%3}, {%4,%5,%6,%7}, {%8,%9}, {%0,%1,%2,%3};\n"
        : "+f"(c[0]), "+f"(c[1]), "+f"(c[2]), "+f"(c[3])
        : "r"(a[0]), "r"(a[1]), "r"(a[2]), "r"(a[3]), "r"(b0), "r"(b1));
}

__global__ __launch_bounds__(THREADS, 2) void ngp_mma_kernel(
    const float* __restrict__ x,
    const float* __restrict__ table,
    const float* __restrict__ w1,
    const float* __restrict__ w2,
    const float* __restrict__ r1,
    const float* __restrict__ r2,
    const float* __restrict__ r3,
    float* __restrict__ out,
    int N, int4 ra, int4 rb)
{
    extern __shared__ char sm[];
    float* s_tab = (float*)(sm + OFF_TAB);
    __nv_bfloat16* w1t = (__nv_bfloat16*)(sm + OFF_W1T);
    __nv_bfloat16* r1t = (__nv_bfloat16*)(sm + OFF_R1T);
    __nv_bfloat16* w2t = (__nv_bfloat16*)(sm + OFF_W2T);
    __nv_bfloat16* r2t = (__nv_bfloat16*)(sm + OFF_R2T);
    __nv_bfloat16* r3t = (__nv_bfloat16*)(sm + OFF_R3T);
    const unsigned* w1t_w = (const unsigned*)w1t;
    const unsigned* r1t_w = (const unsigned*)r1t;
    const unsigned* w2t_w = (const unsigned*)w2t;
    const unsigned* r2t_w = (const unsigned*)r2t;
    const unsigned* r3t_w = (const unsigned*)r3t;

    const int tid = threadIdx.x;
    for (int i = tid; i < 16384; i += THREADS) s_tab[i] = table[i];
    for (int i = tid; i < 1024; i += THREADS) {
        int n = i >> 4, k = i & 15;
        w1t[i] = __float2bfloat16(w1[k * 64 + n]);
        r1t[i] = __float2bfloat16(r1[k * 64 + n]);
    }
    for (int i = tid; i < 1024; i += THREADS) {
        int n = i >> 6, k = i & 63;
        w2t[n * 72 + k] = __float2bfloat16(w2[k * 16 + n]);
    }
    for (int i = tid; i < 4096; i += THREADS) {
        int n = i >> 6, k = i & 63;
        r2t[n * 72 + k] = __float2bfloat16(r2[k * 64 + n]);
    }
    for (int i = tid; i < 576; i += THREADS) {
        int n = i / 72, k = i % 72;
        r3t[i] = __float2bfloat16((n == 0 && k < 64) ? r3[k] : 0.f);
    }
    __syncthreads();

    const int res[8] = {ra.x, ra.y, ra.z, ra.w, rb.x, rb.y, rb.z, rb.w};

    const int warp = tid >> 5, lane = tid & 31;
    const int g = lane >> 2, tig = lane & 3;
    unsigned* stg = (unsigned*)(sm + OFF_STG) + warp * 288;  // 8 kpairs x 36 words

    const int gw = blockIdx.x * WARPS + warp;
    const int nw = CTAS * WARPS;

    for (int base = gw * 32; base < N; base += nw * 32) {
        __syncwarp();
        // ------------ hash-grid encode: one point per lane ------------
        int p = base + lane;
        float hf[16];
        if (p < N) {
            float x01 = x[3 * p + 0] + 0.5f;
            float y01 = x[3 * p + 1] + 0.5f;
            float z01 = x[3 * p + 2] + 0.5f;
            #pragma unroll
            for (int l = 0; l < 8; l++) {
                float rf = (float)res[l];
                float fx = x01 * rf, fy = y01 * rf, fz = z01 * rf;
                float gx = floorf(fx), gy = floorf(fy), gz = floorf(fz);
                float wx = fx - gx, wy = fy - gy, wz = fz - gz;
                unsigned ix = (unsigned)(int)gx;
                unsigned iy = (unsigned)(int)gy;
                unsigned iz = (unsigned)(int)gz;
                unsigned hx0 = ix, hx1 = ix + 1u;
                unsigned hy0 = iy * 2654435761u, hy1 = hy0 + 2654435761u;
                unsigned hz0 = iz * 805459861u,  hz1 = hz0 + 805459861u;
                float wx0 = 1.f - wx, wy0 = 1.f - wy, wz0 = 1.f - wz;
                const float* tl = s_tab + l * 2048;
                float f0 = 0.f, f1 = 0.f;
                #pragma unroll
                for (int c = 0; c < 8; c++) {
                    unsigned h = ((c & 4) ? hx1 : hx0)
                               ^ ((c & 2) ? hy1 : hy0)
                               ^ ((c & 1) ? hz1 : hz0);
                    unsigned idx = h & 1023u;
                    float wgt = ((c & 4) ? wx : wx0)
                              * ((c & 2) ? wy : wy0)
                              * ((c & 1) ? wz : wz0);
                    float2 t = *(const float2*)(tl + idx * 2);
                    f0 = fmaf(wgt, t.x, f0);
                    f1 = fmaf(wgt, t.y, f1);
                }
                hf[l * 2]     = f0;
                hf[l * 2 + 1] = f1;
            }
        } else {
            #pragma unroll
            for (int k = 0; k < 16; k++) hf[k] = 0.f;
        }
        #pragma unroll
        for (int kp = 0; kp < 8; kp++)
            stg[kp * 36 + lane] = pack_bf16(hf[2 * kp], hf[2 * kp + 1]);
        __syncwarp();

        // ------------ two m16 MLP chains per warp ------------
        #pragma unroll
        for (int h = 0; h < 2; h++) {
            unsigned A0[4];
            A0[0] = stg[tig * 36 + h * 16 + g];
            A0[1] = stg[tig * 36 + h * 16 + g + 8];
            A0[2] = stg[(tig + 4) * 36 + h * 16 + g];
            A0[3] = stg[(tig + 4) * 36 + h * 16 + g + 8];

            float C[8][4];
            unsigned A[16];

            // L1: [16,16] x w1[16,64]
            #pragma unroll
            for (int c = 0; c < 8; c++) {
                C[c][0] = C[c][1] = C[c][2] = C[c][3] = 0.f;
                int n = c * 8 + g;
                mma_bf16(C[c], A0, w1t_w[n * 8 + tig], w1t_w[n * 8 + tig + 4]);
            }
            #pragma unroll
            for (int kc = 0; kc < 4; kc++) {
                A[kc * 4 + 0] = pack_bf16(fmaxf(C[2*kc][0], 0.f),   fmaxf(C[2*kc][1], 0.f));
                A[kc * 4 + 1] = pack_bf16(fmaxf(C[2*kc][2], 0.f),   fmaxf(C[2*kc][3], 0.f));
                A[kc * 4 + 2] = pack_bf16(fmaxf(C[2*kc+1][0], 0.f), fmaxf(C[2*kc+1][1], 0.f));
                A[kc * 4 + 3] = pack_bf16(fmaxf(C[2*kc+1][2], 0.f), fmaxf(C[2*kc+1][3], 0.f));
            }

            // L2: [16,64] x w2[64,16] (linear)
            float C2[2][4];
            #pragma unroll
            for (int c = 0; c < 2; c++)
                C2[c][0] = C2[c][1] = C2[c][2] = C2[c][3] = 0.f;
            #pragma unroll
            for (int kc = 0; kc < 4; kc++) {
                #pragma unroll
                for (int c = 0; c < 2; c++) {
                    int n = c * 8 + g;
                    mma_bf16(C2[c], &A[kc * 4],
                             w2t_w[n * 36 + kc * 8 + tig],
                             w2t_w[n * 36 + kc * 8 + tig + 4]);
                }
            }
            unsigned A2[4];
            A2[0] = pack_bf16(C2[0][0], C2[0][1]);
            A2[1] = pack_bf16(C2[0][2], C2[0][3]);
            A2[2] = pack_bf16(C2[1][0], C2[1][1]);
            A2[3] = pack_bf16(C2[1][2], C2[1][3]);

            // L3: [16,16] x r1[16,64]
            #pragma unroll
            for (int c = 0; c < 8; c++) {
                C[c][0] = C[c][1] = C[c][2] = C[c][3] = 0.f;
                int n = c * 8 + g;
                mma_bf16(C[c], A2, r1t_w[n * 8 + tig], r1t_w[n * 8 + tig + 4]);
            }
            #pragma unroll
            for (int kc = 0; kc < 4; kc++) {
                A[kc * 4 + 0] = pack_bf16(fmaxf(C[2*kc][0], 0.f),   fmaxf(C[2*kc][1], 0.f));
                A[kc * 4 + 1] = pack_bf16(fmaxf(C[2*kc][2], 0.f),   fmaxf(C[2*kc][3], 0.f));
                A[kc * 4 + 2] = pack_bf16(fmaxf(C[2*kc+1][0], 0.f), fmaxf(C[2*kc+1][1], 0.f));
                A[kc * 4 + 3] = pack_bf16(fmaxf(C[2*kc+1][2], 0.f), fmaxf(C[2*kc+1][3], 0.f));
            }

            // L4: [16,64] x r2[64,64]
            #pragma unroll
            for (int c = 0; c < 8; c++)
                C[c][0] = C[c][1] = C[c][2] = C[c][3] = 0.f;
            #pragma unroll
            for (int kc = 0; kc < 4; kc++) {
                #pragma unroll
                for (int c = 0; c < 8; c++) {
                    int n = c * 8 + g;
                    mma_bf16(C[c], &A[kc * 4],
                             r2t_w[n * 36 + kc * 8 + tig],
                             r2t_w[n * 36 + kc * 8 + tig + 4]);
                }
            }
            #pragma unroll
            for (int kc = 0; kc < 4; kc++) {
                A[kc * 4 + 0] = pack_bf16(fmaxf(C[2*kc][0], 0.f),   fmaxf(C[2*kc][1], 0.f));
                A[kc * 4 + 1] = pack_bf16(fmaxf(C[2*kc][2], 0.f),   fmaxf(C[2*kc][3], 0.f));
                A[kc * 4 + 2] = pack_bf16(fmaxf(C[2*kc+1][0], 0.f), fmaxf(C[2*kc+1][1], 0.f));
                A[kc * 4 + 3] = pack_bf16(fmaxf(C[2*kc+1][2], 0.f), fmaxf(C[2*kc+1][3], 0.f));
            }

            // L5: [16,64] x r3pad[64,8]
            float C5[4];
            C5[0] = C5[1] = C5[2] = C5[3] = 0.f;
            #pragma unroll
            for (int kc = 0; kc < 4; kc++)
                mma_bf16(C5, &A[kc * 4],
                         r3t_w[g * 36 + kc * 8 + tig],
                         r3t_w[g * 36 + kc * 8 + tig + 4]);

            if (tig == 0) {
                int o0 = base + h * 16 + g;
                int o1 = o0 + 8;
                if (o0 < N) out[o0] = 1.f / (1.f + expf(-C5[0]));
                if (o1 < N) out[o1] = 1.f / (1.f + expf(-C5[2]));
            }
        }
    }
}

extern "C" void kernel_launch(void* const* d_in, const int* in_sizes, int n_in,
                              void* d_out, int out_size) {
    const float* x     = (const float*)d_in[0];
    const float* table = (const float*)d_in[1];
    const float* w1    = (const float*)d_in[2];
    const float* w2    = (const float*)d_in[3];
    const float* r1    = (const float*)d_in[4];
    const float* r2    = (const float*)d_in[5];
    const float* r3    = (const float*)d_in[6];
    float* out = (float*)d_out;
    int N = in_sizes[0] / 3;

    // Replicate numpy's RES computation with host libm (RES[7] sits at 10-1e-14).
    double b = exp(log(5.0) / 7.0);
    int rs[8];
    for (int l = 0; l < 8; l++) rs[l] = (int)floor(2.0 * pow(b, (double)l));
    int4 ra = make_int4(rs[0], rs[1], rs[2], rs[3]);
    int4 rb = make_int4(rs[4], rs[5], rs[6], rs[7]);

    cudaFuncSetAttribute(ngp_mma_kernel, cudaFuncAttributeMaxDynamicSharedMemorySize, SMEM_BYTES);
    ngp_mma_kernel<<<CTAS, THREADS, SMEM_BYTES>>>(x, table, w1, w2, r1, r2, r3,
                                                  out, N, ra, rb);
}

// round 6
// speedup vs baseline: 7.6111x; 1.3027x over previous
#include <cuda_runtime.h>
#include <cuda_bf16.h>
#include <math.h>

#define THREADS 256
#define WARPS 8
#define CTAS 296

// dynamic smem byte offsets
#define OFF_TAB 0                        // 8192 bf16x2 words  (32768 B)
#define OFF_W1T 32768                    // [n=64][k=16] bf16, swizzled (2048 B)
#define OFF_R1T (OFF_W1T + 2048)         // same                        (2048 B)
#define OFF_W2T (OFF_R1T + 2048)         // [n=16][k=72] bf16           (2304 B)
#define OFF_R2T (OFF_W2T + 2304)         // [n=64][k=72] bf16           (9216 B)
#define OFF_R3T (OFF_R2T + 9216)         // [n= 8][k=72] bf16           (1152 B)
#define OFF_STG (OFF_R3T + 1152)         // per warp: 8 kpairs * 40 words (1280 B)
#define SMEM_BYTES (OFF_STG + WARPS * 1280)   // 59776 B

__device__ __forceinline__ unsigned pack_bf16(float lo, float hi) {
    unsigned d;
    asm("cvt.rn.bf16x2.f32 %0, %1, %2;" : "=r"(d) : "f"(hi), "f"(lo));
    return d;
}
__device__ __forceinline__ unsigned packrelu(float a, float b) {
    return pack_bf16(fmaxf(a, 0.f), fmaxf(b, 0.f));
}
__device__ __forceinline__ void mma_bf16(float* c, const unsigned* a,
                                         unsigned b0, unsigned b1) {
    asm volatile(
        "mma.sync.aligned.m16n8k16.row.col.f32.bf16.bf16.f32 "
        "{%0,%1,%2,%3}, {%4,%5,%6,%7}, {%8,%9}, {%0,%1,%2,%3};\n"
        : "+f"(c[0]), "+f"(c[1]), "+f"(c[2]), "+f"(c[3])
        : "r"(a[0]), "r"(a[1]), "r"(a[2]), "r"(a[3]), "r"(b0), "r"(b1));
}

__global__ __launch_bounds__(THREADS, 2) void ngp_mma_kernel(
    const float* __restrict__ x,
    const float* __restrict__ table,
    const float* __restrict__ w1,
    const float* __restrict__ w2,
    const float* __restrict__ r1,
    const float* __restrict__ r2,
    const float* __restrict__ r3,
    float* __restrict__ out,
    int N, int4 ra, int4 rb)
{
    extern __shared__ char sm[];
    unsigned* s_tab = (unsigned*)(sm + OFF_TAB);       // bf16x2 per entry
    __nv_bfloat16* w1t = (__nv_bfloat16*)(sm + OFF_W1T);
    __nv_bfloat16* r1t = (__nv_bfloat16*)(sm + OFF_R1T);
    __nv_bfloat16* w2t = (__nv_bfloat16*)(sm + OFF_W2T);
    __nv_bfloat16* r2t = (__nv_bfloat16*)(sm + OFF_R2T);
    __nv_bfloat16* r3t = (__nv_bfloat16*)(sm + OFF_R3T);
    const unsigned* w1t_w = (const unsigned*)w1t;
    const unsigned* r1t_w = (const unsigned*)r1t;
    const unsigned* w2t_w = (const unsigned*)w2t;
    const unsigned* r2t_w = (const unsigned*)r2t;
    const unsigned* r3t_w = (const unsigned*)r3t;

    const int tid = threadIdx.x;
    for (int i = tid; i < 8192; i += THREADS) {
        float2 t = ((const float2*)table)[i];
        s_tab[i] = pack_bf16(t.x, t.y);
    }
    for (int i = tid; i < 1024; i += THREADS) {
        int n = i >> 4, k = i & 15;
        // word-swizzled: word w = n*8 + (k>>1), ws = w ^ (((n>>2)&1)<<2)
        int ws = (n * 8 + (k >> 1)) ^ (((n >> 2) & 1) << 2);
        int e = ws * 2 + (k & 1);
        w1t[e] = __float2bfloat16(w1[k * 64 + n]);
        r1t[e] = __float2bfloat16(r1[k * 64 + n]);
    }
    for (int i = tid; i < 1024; i += THREADS) {
        int n = i >> 6, k = i & 63;
        w2t[n * 72 + k] = __float2bfloat16(w2[k * 16 + n]);
    }
    for (int i = tid; i < 4096; i += THREADS) {
        int n = i >> 6, k = i & 63;
        r2t[n * 72 + k] = __float2bfloat16(r2[k * 64 + n]);
    }
    for (int i = tid; i < 576; i += THREADS) {
        int n = i / 72, k = i % 72;
        r3t[i] = __float2bfloat16((n == 0 && k < 64) ? r3[k] : 0.f);
    }
    __syncthreads();

    const int res[8] = {ra.x, ra.y, ra.z, ra.w, rb.x, rb.y, rb.z, rb.w};

    const int warp = tid >> 5, lane = tid & 31;
    const int g = lane >> 2, tig = lane & 3;
    const unsigned sw14 = ((g >> 2) & 1) << 2;   // swizzle term for w1t/r1t loads
    unsigned* stg = (unsigned*)(sm + OFF_STG) + warp * 320;  // 8 kpairs x 40 words

    const int gw = blockIdx.x * WARPS + warp;
    const int nw = CTAS * WARPS;

    for (int base = gw * 32; base < N; base += nw * 32) {
        __syncwarp();
        // ------------ hash-grid encode: one point per lane ------------
        int p = base + lane;
        unsigned hfp[8];
        if (p < N) {
            float x01 = x[3 * p + 0] + 0.5f;
            float y01 = x[3 * p + 1] + 0.5f;
            float z01 = x[3 * p + 2] + 0.5f;
            #pragma unroll
            for (int l = 0; l < 8; l++) {
                float rf = (float)res[l];
                float fx = x01 * rf, fy = y01 * rf, fz = z01 * rf;
                float gx = floorf(fx), gy = floorf(fy), gz = floorf(fz);
                float wx = fx - gx, wy = fy - gy, wz = fz - gz;
                unsigned ix = (unsigned)(int)gx;
                unsigned iy = (unsigned)(int)gy;
                unsigned iz = (unsigned)(int)gz;
                unsigned hx0 = ix, hx1 = ix + 1u;
                unsigned hy0 = iy * 2654435761u, hy1 = hy0 + 2654435761u;
                unsigned hz0 = iz * 805459861u,  hz1 = hz0 + 805459861u;
                float wx0 = 1.f - wx, wy0 = 1.f - wy, wz0 = 1.f - wz;
                // 4 xy weight products
                float w00 = wx0 * wy0, w01 = wx0 * wy;
                float w10 = wx * wy0,  w11 = wx * wy;
                const unsigned* tl = s_tab + l * 1024;
                __nv_bfloat162 acc = __floats2bfloat162_rn(0.f, 0.f);
                #pragma unroll
                for (int c = 0; c < 8; c++) {
                    unsigned h = ((c & 4) ? hx1 : hx0)
                               ^ ((c & 2) ? hy1 : hy0)
                               ^ ((c & 1) ? hz1 : hz0);
                    unsigned idx = h & 1023u;
                    float wxy = (c & 4) ? ((c & 2) ? w11 : w10)
                                        : ((c & 2) ? w01 : w00);
                    float wgt = wxy * ((c & 1) ? wz : wz0);
                    unsigned wd = pack_bf16(wgt, wgt);
                    unsigned td = tl[idx];
                    acc = __hfma2(*(__nv_bfloat162*)&wd, *(__nv_bfloat162*)&td, acc);
                }
                hfp[l] = *(unsigned*)&acc;
            }
        } else {
            #pragma unroll
            for (int l = 0; l < 8; l++) hfp[l] = 0u;
        }
        #pragma unroll
        for (int kp = 0; kp < 8; kp++)
            stg[kp * 40 + lane] = hfp[kp];
        __syncwarp();

        // ------------ A0 fragments for both 16-point chains ------------
        unsigned A0h0[4], A0h1[4];
        A0h0[0] = stg[tig * 40 + g];
        A0h0[1] = stg[tig * 40 + g + 8];
        A0h0[2] = stg[(tig + 4) * 40 + g];
        A0h0[3] = stg[(tig + 4) * 40 + g + 8];
        A0h1[0] = stg[tig * 40 + 16 + g];
        A0h1[1] = stg[tig * 40 + 16 + g + 8];
        A0h1[2] = stg[(tig + 4) * 40 + 16 + g];
        A0h1[3] = stg[(tig + 4) * 40 + 16 + g + 8];

        // ------------ L1: 16 -> 64, relu (B shared across chains) ------------
        unsigned A1h0[16], A1h1[16];
        #pragma unroll
        for (int cp = 0; cp < 4; cp++) {
            float Ca0[4] = {0,0,0,0}, Ca1[4] = {0,0,0,0};
            float Cb0[4] = {0,0,0,0}, Cb1[4] = {0,0,0,0};
            int na = 16 * cp + g, nb = na + 8;
            unsigned ba0 = w1t_w[(na * 8 + tig) ^ sw14];
            unsigned ba1 = w1t_w[(na * 8 + tig + 4) ^ sw14];
            unsigned bb0 = w1t_w[(nb * 8 + tig) ^ sw14];
            unsigned bb1 = w1t_w[(nb * 8 + tig + 4) ^ sw14];
            mma_bf16(Ca0, A0h0, ba0, ba1);
            mma_bf16(Ca1, A0h1, ba0, ba1);
            mma_bf16(Cb0, A0h0, bb0, bb1);
            mma_bf16(Cb1, A0h1, bb0, bb1);
            A1h0[cp*4+0] = packrelu(Ca0[0], Ca0[1]);
            A1h0[cp*4+1] = packrelu(Ca0[2], Ca0[3]);
            A1h0[cp*4+2] = packrelu(Cb0[0], Cb0[1]);
            A1h0[cp*4+3] = packrelu(Cb0[2], Cb0[3]);
            A1h1[cp*4+0] = packrelu(Ca1[0], Ca1[1]);
            A1h1[cp*4+1] = packrelu(Ca1[2], Ca1[3]);
            A1h1[cp*4+2] = packrelu(Cb1[0], Cb1[1]);
            A1h1[cp*4+3] = packrelu(Cb1[2], Cb1[3]);
        }

        // ------------ L2: 64 -> 16, linear ------------
        unsigned A2h0[4], A2h1[4];
        {
            float C0h0[4] = {0,0,0,0}, C0h1[4] = {0,0,0,0};
            float C1h0[4] = {0,0,0,0}, C1h1[4] = {0,0,0,0};
            #pragma unroll
            for (int kc = 0; kc < 4; kc++) {
                unsigned b00 = w2t_w[g * 36 + kc * 8 + tig];
                unsigned b01 = w2t_w[g * 36 + kc * 8 + tig + 4];
                unsigned b10 = w2t_w[(8 + g) * 36 + kc * 8 + tig];
                unsigned b11 = w2t_w[(8 + g) * 36 + kc * 8 + tig + 4];
                mma_bf16(C0h0, &A1h0[kc*4], b00, b01);
                mma_bf16(C0h1, &A1h1[kc*4], b00, b01);
                mma_bf16(C1h0, &A1h0[kc*4], b10, b11);
                mma_bf16(C1h1, &A1h1[kc*4], b10, b11);
            }
            A2h0[0] = pack_bf16(C0h0[0], C0h0[1]);
            A2h0[1] = pack_bf16(C0h0[2], C0h0[3]);
            A2h0[2] = pack_bf16(C1h0[0], C1h0[1]);
            A2h0[3] = pack_bf16(C1h0[2], C1h0[3]);
            A2h1[0] = pack_bf16(C0h1[0], C0h1[1]);
            A2h1[1] = pack_bf16(C0h1[2], C0h1[3]);
            A2h1[2] = pack_bf16(C1h1[0], C1h1[1]);
            A2h1[3] = pack_bf16(C1h1[2], C1h1[3]);
        }

        // ------------ L3: 16 -> 64, relu ------------
        unsigned A3h0[16], A3h1[16];
        #pragma unroll
        for (int cp = 0; cp < 4; cp++) {
            float Ca0[4] = {0,0,0,0}, Ca1[4] = {0,0,0,0};
            float Cb0[4] = {0,0,0,0}, Cb1[4] = {0,0,0,0};
            int na = 16 * cp + g, nb = na + 8;
            unsigned ba0 = r1t_w[(na * 8 + tig) ^ sw14];
            unsigned ba1 = r1t_w[(na * 8 + tig + 4) ^ sw14];
            unsigned bb0 = r1t_w[(nb * 8 + tig) ^ sw14];
            unsigned bb1 = r1t_w[(nb * 8 + tig + 4) ^ sw14];
            mma_bf16(Ca0, A2h0, ba0, ba1);
            mma_bf16(Ca1, A2h1, ba0, ba1);
            mma_bf16(Cb0, A2h0, bb0, bb1);
            mma_bf16(Cb1, A2h1, bb0, bb1);
            A3h0[cp*4+0] = packrelu(Ca0[0], Ca0[1]);
            A3h0[cp*4+1] = packrelu(Ca0[2], Ca0[3]);
            A3h0[cp*4+2] = packrelu(Cb0[0], Cb0[1]);
            A3h0[cp*4+3] = packrelu(Cb0[2], Cb0[3]);
            A3h1[cp*4+0] = packrelu(Ca1[0], Ca1[1]);
            A3h1[cp*4+1] = packrelu(Ca1[2], Ca1[3]);
            A3h1[cp*4+2] = packrelu(Cb1[0], Cb1[1]);
            A3h1[cp*4+3] = packrelu(Cb1[2], Cb1[3]);
        }

        // ------------ L4: 64 -> 64, relu ------------
        unsigned Gh0[16], Gh1[16];
        #pragma unroll
        for (int cp = 0; cp < 4; cp++) {
            float Ca0[4] = {0,0,0,0}, Ca1[4] = {0,0,0,0};
            float Cb0[4] = {0,0,0,0}, Cb1[4] = {0,0,0,0};
            int na = 16 * cp + g, nb = na + 8;
            #pragma unroll
            for (int kc = 0; kc < 4; kc++) {
                unsigned ba0 = r2t_w[na * 36 + kc * 8 + tig];
                unsigned ba1 = r2t_w[na * 36 + kc * 8 + tig + 4];
                unsigned bb0 = r2t_w[nb * 36 + kc * 8 + tig];
                unsigned bb1 = r2t_w[nb * 36 + kc * 8 + tig + 4];
                mma_bf16(Ca0, &A3h0[kc*4], ba0, ba1);
                mma_bf16(Ca1, &A3h1[kc*4], ba0, ba1);
                mma_bf16(Cb0, &A3h0[kc*4], bb0, bb1);
                mma_bf16(Cb1, &A3h1[kc*4], bb0, bb1);
            }
            Gh0[cp*4+0] = packrelu(Ca0[0], Ca0[1]);
            Gh0[cp*4+1] = packrelu(Ca0[2], Ca0[3]);
            Gh0[cp*4+2] = packrelu(Cb0[0], Cb0[1]);
            Gh0[cp*4+3] = packrelu(Cb0[2], Cb0[3]);
            Gh1[cp*4+0] = packrelu(Ca1[0], Ca1[1]);
            Gh1[cp*4+1] = packrelu(Ca1[2], Ca1[3]);
            Gh1[cp*4+2] = packrelu(Cb1[0], Cb1[1]);
            Gh1[cp*4+3] = packrelu(Cb1[2], Cb1[3]);
        }

        // ------------ L5: 64 -> 1 (+sigmoid) ------------
        float C5h0[4] = {0,0,0,0}, C5h1[4] = {0,0,0,0};
        #pragma unroll
        for (int kc = 0; kc < 4; kc++) {
            unsigned b0 = r3t_w[g * 36 + kc * 8 + tig];
            unsigned b1 = r3t_w[g * 36 + kc * 8 + tig + 4];
            mma_bf16(C5h0, &Gh0[kc*4], b0, b1);
            mma_bf16(C5h1, &Gh1[kc*4], b0, b1);
        }
        if (tig == 0) {
            int o = base + g;
            if (o < N)      out[o]      = 1.f / (1.f + __expf(-C5h0[0]));
            if (o + 8 < N)  out[o + 8]  = 1.f / (1.f + __expf(-C5h0[2]));
            if (o + 16 < N) out[o + 16] = 1.f / (1.f + __expf(-C5h1[0]));
            if (o + 24 < N) out[o + 24] = 1.f / (1.f + __expf(-C5h1[2]));
        }
    }
}

extern "C" void kernel_launch(void* const* d_in, const int* in_sizes, int n_in,
                              void* d_out, int out_size) {
    const float* x     = (const float*)d_in[0];
    const float* table = (const float*)d_in[1];
    const float* w1    = (const float*)d_in[2];
    const float* w2    = (const float*)d_in[3];
    const float* r1    = (const float*)d_in[4];
    const float* r2    = (const float*)d_in[5];
    const float* r3    = (const float*)d_in[6];
    float* out = (float*)d_out;
    int N = in_sizes[0] / 3;

    // Replicate numpy's RES computation with host libm (RES[7] sits at 10-1e-14).
    double b = exp(log(5.0) / 7.0);
    int rs[8];
    for (int l = 0; l < 8; l++) rs[l] = (int)floor(2.0 * pow(b, (double)l));
    int4 ra = make_int4(rs[0], rs[1], rs[2], rs[3]);
    int4 rb = make_int4(rs[4], rs[5], rs[6], rs[7]);

    cudaFuncSetAttribute(ngp_mma_kernel, cudaFuncAttributeMaxDynamicSharedMemorySize, SMEM_BYTES);
    ngp_mma_kernel<<<CTAS, THREADS, SMEM_BYTES>>>(x, table, w1, w2, r1, r2, r3,
                                                  out, N, ra, rb);
}

// round 7
// speedup vs baseline: 8.1346x; 1.0688x over previous
#include <cuda_runtime.h>
#include <cuda_bf16.h>
#include <math.h>

#define THREADS 256
#define WARPS 8
#define CTAS 296

// dynamic smem byte offsets
#define OFF_TAB 0                        // 8192 bf16x2 words            (32768 B)
#define OFF_W1T 32768                    // [n=64][8w] pair layout        (2048 B)
#define OFF_R1T (OFF_W1T + 2048)         // same                          (2048 B)
#define OFF_W2T (OFF_R1T + 2048)         // [n=16][40w] pair layout       (2560 B)
#define OFF_R2T (OFF_W2T + 2560)         // [n=64][40w]                  (10240 B)
#define OFF_R3T (OFF_R2T + 10240)        // [n= 8][40w]                   (1280 B)
#define OFF_STG (OFF_R3T + 1280)         // per warp: 8 kpairs * 40 words (1280 B)
#define SMEM_BYTES (OFF_STG + WARPS * 1280)   // 61184 B

__device__ __forceinline__ unsigned pack_bf16(float lo, float hi) {
    unsigned d;
    asm("cvt.rn.bf16x2.f32 %0, %1, %2;" : "=r"(d) : "f"(hi), "f"(lo));
    return d;
}
__device__ __forceinline__ unsigned packrelu(float a, float b) {
    unsigned d = pack_bf16(a, b);
    __nv_bfloat162 z = __float2bfloat162_rn(0.f);
    __nv_bfloat162 v = __hmax2(*(__nv_bfloat162*)&d, z);
    return *(unsigned*)&v;
}
__device__ __forceinline__ void mma_bf16(float* c, const unsigned* a,
                                         unsigned b0, unsigned b1) {
    asm volatile(
        "mma.sync.aligned.m16n8k16.row.col.f32.bf16.bf16.f32 "
        "{%0,%1,%2,%3}, {%4,%5,%6,%7}, {%8,%9}, {%0,%1,%2,%3};\n"
        : "+f"(c[0]), "+f"(c[1]), "+f"(c[2]), "+f"(c[3])
        : "r"(a[0]), "r"(a[1]), "r"(a[2]), "r"(a[3]), "r"(b0), "r"(b1));
}

// element index for k16 pair layout (w1t/r1t): word = n*8 + tig*2 + j
__device__ __forceinline__ int e_k16(int n, int k) {
    int tig = (k >> 1) & 3, j = (k >> 3) & 1;
    return (n * 8 + tig * 2 + j) * 2 + (k & 1);
}
// element index for k64 pair layout (w2t/r2t/r3t): word = n*40 + kc*8 + tig*2 + j
__device__ __forceinline__ int e_k64(int n, int k) {
    int kc = k >> 4, kk = k & 15;
    int tig = (kk >> 1) & 3, j = (kk >> 3) & 1;
    return (n * 40 + kc * 8 + tig * 2 + j) * 2 + (k & 1);
}

__global__ __launch_bounds__(THREADS, 2) void ngp_mma_kernel(
    const float* __restrict__ x,
    const float* __restrict__ table,
    const float* __restrict__ w1,
    const float* __restrict__ w2,
    const float* __restrict__ r1,
    const float* __restrict__ r2,
    const float* __restrict__ r3,
    float* __restrict__ out,
    int N, int4 ra, int4 rb)
{
    extern __shared__ char sm[];
    unsigned* s_tab = (unsigned*)(sm + OFF_TAB);       // bf16x2 per entry
    __nv_bfloat16* w1t = (__nv_bfloat16*)(sm + OFF_W1T);
    __nv_bfloat16* r1t = (__nv_bfloat16*)(sm + OFF_R1T);
    __nv_bfloat16* w2t = (__nv_bfloat16*)(sm + OFF_W2T);
    __nv_bfloat16* r2t = (__nv_bfloat16*)(sm + OFF_R2T);
    __nv_bfloat16* r3t = (__nv_bfloat16*)(sm + OFF_R3T);
    const unsigned* w1t_w = (const unsigned*)w1t;
    const unsigned* r1t_w = (const unsigned*)r1t;
    const unsigned* w2t_w = (const unsigned*)w2t;
    const unsigned* r2t_w = (const unsigned*)r2t;
    const unsigned* r3t_w = (const unsigned*)r3t;

    const int tid = threadIdx.x;
    for (int i = tid; i < 8192; i += THREADS) {
        float2 t = ((const float2*)table)[i];
        s_tab[i] = pack_bf16(t.x, t.y);
    }
    for (int i = tid; i < 1024; i += THREADS) {
        int n = i >> 4, k = i & 15;
        int e = e_k16(n, k);
        w1t[e] = __float2bfloat16(w1[k * 64 + n]);
        r1t[e] = __float2bfloat16(r1[k * 64 + n]);
    }
    for (int i = tid; i < 1024; i += THREADS) {
        int n = i >> 6, k = i & 63;
        w2t[e_k64(n, k)] = __float2bfloat16(w2[k * 16 + n]);
    }
    for (int i = tid; i < 4096; i += THREADS) {
        int n = i >> 6, k = i & 63;
        r2t[e_k64(n, k)] = __float2bfloat16(r2[k * 64 + n]);
    }
    for (int i = tid; i < 640; i += THREADS) {   // 8 rows * 40 words * 2 elems
        int word = i >> 1;
        int n = word / 40, rem = word % 40;
        int kc = rem >> 3, tig = (rem >> 1) & 3, j = rem & 1;
        int k = kc * 16 + j * 8 + tig * 2 + (i & 1);
        r3t[i] = __float2bfloat16((n == 0 && rem < 32) ? r3[k] : 0.f);
    }
    __syncthreads();

    const int res[8] = {ra.x, ra.y, ra.z, ra.w, rb.x, rb.y, rb.z, rb.w};

    const int warp = tid >> 5, lane = tid & 31;
    const int g = lane >> 2, tig = lane & 3;
    unsigned* stg = (unsigned*)(sm + OFF_STG) + warp * 320;  // 8 kpairs x 40 words

    const int gw = blockIdx.x * WARPS + warp;
    const int nw = CTAS * WARPS;

    for (int base = gw * 32; base < N; base += nw * 32) {
        __syncwarp();
        // ------------ hash-grid encode: one point per lane ------------
        int p = base + lane;
        unsigned hfp[8];
        if (p < N) {
            float x01 = x[3 * p + 0] + 0.5f;
            float y01 = x[3 * p + 1] + 0.5f;
            float z01 = x[3 * p + 2] + 0.5f;
            #pragma unroll
            for (int l = 0; l < 8; l++) {
                float rf = (float)res[l];
                float fx = x01 * rf, fy = y01 * rf, fz = z01 * rf;
                float gx = floorf(fx), gy = floorf(fy), gz = floorf(fz);
                float wx = fx - gx, wy = fy - gy, wz = fz - gz;
                unsigned ix = (unsigned)(int)gx;
                unsigned iy = (unsigned)(int)gy;
                unsigned iz = (unsigned)(int)gz;
                unsigned hx0 = ix, hx1 = ix + 1u;
                unsigned hy0 = iy * 2654435761u, hy1 = hy0 + 2654435761u;
                unsigned hz0 = iz * 805459861u,  hz1 = hz0 + 805459861u;
                float wx0 = 1.f - wx, wy0 = 1.f - wy, wz0 = 1.f - wz;
                float w00 = wx0 * wy0, w01 = wx0 * wy;
                float w10 = wx * wy0,  w11 = wx * wy;
                const unsigned* tl = s_tab + l * 1024;
                __nv_bfloat162 acc0 = __floats2bfloat162_rn(0.f, 0.f);
                __nv_bfloat162 acc1 = acc0;
                #pragma unroll
                for (int c = 0; c < 8; c += 2) {
                    unsigned hbase = ((c & 4) ? hx1 : hx0)
                                   ^ ((c & 2) ? hy1 : hy0);
                    float wxy = (c & 4) ? ((c & 2) ? w11 : w10)
                                        : ((c & 2) ? w01 : w00);
                    unsigned idx0 = (hbase ^ hz0) & 1023u;
                    unsigned idx1 = (hbase ^ hz1) & 1023u;
                    float wgt0 = wxy * wz0;
                    float wgt1 = wxy * wz;
                    unsigned wd0 = pack_bf16(wgt0, wgt0);
                    unsigned wd1 = pack_bf16(wgt1, wgt1);
                    unsigned td0 = tl[idx0];
                    unsigned td1 = tl[idx1];
                    acc0 = __hfma2(*(__nv_bfloat162*)&wd0, *(__nv_bfloat162*)&td0, acc0);
                    acc1 = __hfma2(*(__nv_bfloat162*)&wd1, *(__nv_bfloat162*)&td1, acc1);
                }
                __nv_bfloat162 acc = __hadd2(acc0, acc1);
                hfp[l] = *(unsigned*)&acc;
            }
        } else {
            #pragma unroll
            for (int l = 0; l < 8; l++) hfp[l] = 0u;
        }
        #pragma unroll
        for (int kp = 0; kp < 8; kp++)
            stg[kp * 40 + lane] = hfp[kp];
        __syncwarp();

        // ------------ A0 fragments for both 16-point chains ------------
        unsigned A0h0[4], A0h1[4];
        A0h0[0] = stg[tig * 40 + g];
        A0h0[1] = stg[tig * 40 + g + 8];
        A0h0[2] = stg[(tig + 4) * 40 + g];
        A0h0[3] = stg[(tig + 4) * 40 + g + 8];
        A0h1[0] = stg[tig * 40 + 16 + g];
        A0h1[1] = stg[tig * 40 + 16 + g + 8];
        A0h1[2] = stg[(tig + 4) * 40 + 16 + g];
        A0h1[3] = stg[(tig + 4) * 40 + 16 + g + 8];

        // ------------ L1: 16 -> 64, relu (B shared across chains) ------------
        unsigned A1h0[16], A1h1[16];
        #pragma unroll
        for (int cp = 0; cp < 4; cp++) {
            float Ca0[4] = {0,0,0,0}, Ca1[4] = {0,0,0,0};
            float Cb0[4] = {0,0,0,0}, Cb1[4] = {0,0,0,0};
            int na = 16 * cp + g, nb = na + 8;
            uint2 ba = *(const uint2*)(w1t_w + na * 8 + tig * 2);
            uint2 bb = *(const uint2*)(w1t_w + nb * 8 + tig * 2);
            mma_bf16(Ca0, A0h0, ba.x, ba.y);
            mma_bf16(Ca1, A0h1, ba.x, ba.y);
            mma_bf16(Cb0, A0h0, bb.x, bb.y);
            mma_bf16(Cb1, A0h1, bb.x, bb.y);
            A1h0[cp*4+0] = packrelu(Ca0[0], Ca0[1]);
            A1h0[cp*4+1] = packrelu(Ca0[2], Ca0[3]);
            A1h0[cp*4+2] = packrelu(Cb0[0], Cb0[1]);
            A1h0[cp*4+3] = packrelu(Cb0[2], Cb0[3]);
            A1h1[cp*4+0] = packrelu(Ca1[0], Ca1[1]);
            A1h1[cp*4+1] = packrelu(Ca1[2], Ca1[3]);
            A1h1[cp*4+2] = packrelu(Cb1[0], Cb1[1]);
            A1h1[cp*4+3] = packrelu(Cb1[2], Cb1[3]);
        }

        // ------------ L2: 64 -> 16, linear ------------
        unsigned A2h0[4], A2h1[4];
        {
            float C0h0[4] = {0,0,0,0}, C0h1[4] = {0,0,0,0};
            float C1h0[4] = {0,0,0,0}, C1h1[4] = {0,0,0,0};
            #pragma unroll
            for (int kc = 0; kc < 4; kc++) {
                uint2 b0 = *(const uint2*)(w2t_w + g * 40 + kc * 8 + tig * 2);
                uint2 b1 = *(const uint2*)(w2t_w + (8 + g) * 40 + kc * 8 + tig * 2);
                mma_bf16(C0h0, &A1h0[kc*4], b0.x, b0.y);
                mma_bf16(C0h1, &A1h1[kc*4], b0.x, b0.y);
                mma_bf16(C1h0, &A1h0[kc*4], b1.x, b1.y);
                mma_bf16(C1h1, &A1h1[kc*4], b1.x, b1.y);
            }
            A2h0[0] = pack_bf16(C0h0[0], C0h0[1]);
            A2h0[1] = pack_bf16(C0h0[2], C0h0[3]);
            A2h0[2] = pack_bf16(C1h0[0], C1h0[1]);
            A2h0[3] = pack_bf16(C1h0[2], C1h0[3]);
            A2h1[0] = pack_bf16(C0h1[0], C0h1[1]);
            A2h1[1] = pack_bf16(C0h1[2], C0h1[3]);
            A2h1[2] = pack_bf16(C1h1[0], C1h1[1]);
            A2h1[3] = pack_bf16(C1h1[2], C1h1[3]);
        }

        // ------------ L3: 16 -> 64, relu ------------
        unsigned A3h0[16], A3h1[16];
        #pragma unroll
        for (int cp = 0; cp < 4; cp++) {
            float Ca0[4] = {0,0,0,0}, Ca1[4] = {0,0,0,0};
            float Cb0[4] = {0,0,0,0}, Cb1[4] = {0,0,0,0};
            int na = 16 * cp + g, nb = na + 8;
            uint2 ba = *(const uint2*)(r1t_w + na * 8 + tig * 2);
            uint2 bb = *(const uint2*)(r1t_w + nb * 8 + tig * 2);
            mma_bf16(Ca0, A2h0, ba.x, ba.y);
            mma_bf16(Ca1, A2h1, ba.x, ba.y);
            mma_bf16(Cb0, A2h0, bb.x, bb.y);
            mma_bf16(Cb1, A2h1, bb.x, bb.y);
            A3h0[cp*4+0] = packrelu(Ca0[0], Ca0[1]);
            A3h0[cp*4+1] = packrelu(Ca0[2], Ca0[3]);
            A3h0[cp*4+2] = packrelu(Cb0[0], Cb0[1]);
            A3h0[cp*4+3] = packrelu(Cb0[2], Cb0[3]);
            A3h1[cp*4+0] = packrelu(Ca1[0], Ca1[1]);
            A3h1[cp*4+1] = packrelu(Ca1[2], Ca1[3]);
            A3h1[cp*4+2] = packrelu(Cb1[0], Cb1[1]);
            A3h1[cp*4+3] = packrelu(Cb1[2], Cb1[3]);
        }

        // ------------ L4: 64 -> 64, relu ------------
        unsigned Gh0[16], Gh1[16];
        #pragma unroll
        for (int cp = 0; cp < 4; cp++) {
            float Ca0[4] = {0,0,0,0}, Ca1[4] = {0,0,0,0};
            float Cb0[4] = {0,0,0,0}, Cb1[4] = {0,0,0,0};
            int na = 16 * cp + g, nb = na + 8;
            #pragma unroll
            for (int kc = 0; kc < 4; kc++) {
                uint2 ba = *(const uint2*)(r2t_w + na * 40 + kc * 8 + tig * 2);
                uint2 bb = *(const uint2*)(r2t_w + nb * 40 + kc * 8 + tig * 2);
                mma_bf16(Ca0, &A3h0[kc*4], ba.x, ba.y);
                mma_bf16(Ca1, &A3h1[kc*4], ba.x, ba.y);
                mma_bf16(Cb0, &A3h0[kc*4], bb.x, bb.y);
                mma_bf16(Cb1, &A3h1[kc*4], bb.x, bb.y);
            }
            Gh0[cp*4+0] = packrelu(Ca0[0], Ca0[1]);
            Gh0[cp*4+1] = packrelu(Ca0[2], Ca0[3]);
            Gh0[cp*4+2] = packrelu(Cb0[0], Cb0[1]);
            Gh0[cp*4+3] = packrelu(Cb0[2], Cb0[3]);
            Gh1[cp*4+0] = packrelu(Ca1[0], Ca1[1]);
            Gh1[cp*4+1] = packrelu(Ca1[2], Ca1[3]);
            Gh1[cp*4+2] = packrelu(Cb1[0], Cb1[1]);
            Gh1[cp*4+3] = packrelu(Cb1[2], Cb1[3]);
        }

        // ------------ L5: 64 -> 1 (+sigmoid) ------------
        float C5h0[4] = {0,0,0,0}, C5h1[4] = {0,0,0,0};
        #pragma unroll
        for (int kc = 0; kc < 4; kc++) {
            uint2 b = *(const uint2*)(r3t_w + g * 40 + kc * 8 + tig * 2);
            mma_bf16(C5h0, &Gh0[kc*4], b.x, b.y);
            mma_bf16(C5h1, &Gh1[kc*4], b.x, b.y);
        }
        if (tig == 0) {
            int o = base + g;
            if (o < N)      out[o]      = 1.f / (1.f + __expf(-C5h0[0]));
            if (o + 8 < N)  out[o + 8]  = 1.f / (1.f + __expf(-C5h0[2]));
            if (o + 16 < N) out[o + 16] = 1.f / (1.f + __expf(-C5h1[0]));
            if (o + 24 < N) out[o + 24] = 1.f / (1.f + __expf(-C5h1[2]));
        }
    }
}

extern "C" void kernel_launch(void* const* d_in, const int* in_sizes, int n_in,
                              void* d_out, int out_size) {
    const float* x     = (const float*)d_in[0];
    const float* table = (const float*)d_in[1];
    const float* w1    = (const float*)d_in[2];
    const float* w2    = (const float*)d_in[3];
    const float* r1    = (const float*)d_in[4];
    const float* r2    = (const float*)d_in[5];
    const float* r3    = (const float*)d_in[6];
    float* out = (float*)d_out;
    int N = in_sizes[0] / 3;

    // Replicate numpy's RES computation with host libm (RES[7] sits at 10-1e-14).
    double b = exp(log(5.0) / 7.0);
    int rs[8];
    for (int l = 0; l < 8; l++) rs[l] = (int)floor(2.0 * pow(b, (double)l));
    int4 ra = make_int4(rs[0], rs[1], rs[2], rs[3]);
    int4 rb = make_int4(rs[4], rs[5], rs[6], rs[7]);

    cudaFuncSetAttribute(ngp_mma_kernel, cudaFuncAttributeMaxDynamicSharedMemorySize, SMEM_BYTES);
    ngp_mma_kernel<<<CTAS, THREADS, SMEM_BYTES>>>(x, table, w1, w2, r1, r2, r3,
                                                  out, N, ra, rb);
}